// round 1
// baseline (speedup 1.0000x reference)
#include <cuda_runtime.h>
#include <cuda_bf16.h>
#include <cstdint>

// ---------------------------------------------------------------------------
// PerceiverAttentionCA: fp32 SIMT baseline
//   xn = LN(x); ln = LN(latents)
//   q = ln @ w_q ; kv = xn @ w_kv ; k,v = split(kv)
//   S = (q kT)/sqrt(128) per (b,h); P = softmax(S); att = P v
//   out = att @ w_out
// ---------------------------------------------------------------------------

#define B_SZ 2
#define N1 2048
#define N2 2048
#define DIM 3072
#define KV_DIM 2048
#define HEADS 16
#define DHEAD 128
#define INNER 2048

// scratch (static device globals; allocation APIs are forbidden)
__device__ __align__(16) float g_xn[(size_t)B_SZ * N1 * KV_DIM];        // 32 MB
__device__ __align__(16) float g_ln[(size_t)B_SZ * N2 * DIM];           // 48 MB
__device__ __align__(16) float g_q [(size_t)B_SZ * N2 * INNER];         // 32 MB
__device__ __align__(16) float g_kv[(size_t)B_SZ * N1 * 2 * INNER];     // 64 MB
__device__ __align__(16) float g_s [(size_t)B_SZ * HEADS * N2 * N1];    // 512 MB
__device__ __align__(16) float g_at[(size_t)B_SZ * N2 * INNER];         // 32 MB

// ---------------------------------------------------------------------------
// LayerNorm: one block per row
// ---------------------------------------------------------------------------
__global__ void __launch_bounds__(256) ln_kernel(
    const float* __restrict__ x, const float* __restrict__ gam,
    const float* __restrict__ bet, float* __restrict__ out, int cols)
{
    const int row = blockIdx.x;
    const float* xr = x + (size_t)row * cols;
    float* orow = out + (size_t)row * cols;

    float s = 0.f, s2 = 0.f;
    for (int i = threadIdx.x; i < cols; i += blockDim.x) {
        float v = xr[i];
        s += v; s2 += v * v;
    }
    __shared__ float sm0[8], sm1[8];
    #pragma unroll
    for (int o = 16; o > 0; o >>= 1) {
        s  += __shfl_down_sync(0xffffffffu, s,  o);
        s2 += __shfl_down_sync(0xffffffffu, s2, o);
    }
    int w = threadIdx.x >> 5, l = threadIdx.x & 31;
    if (l == 0) { sm0[w] = s; sm1[w] = s2; }
    __syncthreads();
    if (threadIdx.x == 0) {
        float ts = 0.f, t2 = 0.f;
        #pragma unroll
        for (int i = 0; i < 8; i++) { ts += sm0[i]; t2 += sm1[i]; }
        float mu  = ts / (float)cols;
        float var = t2 / (float)cols - mu * mu;
        sm0[0] = mu;
        sm1[0] = rsqrtf(var + 1e-5f);
    }
    __syncthreads();
    float mu = sm0[0], rs = sm1[0];
    for (int i = threadIdx.x; i < cols; i += blockDim.x) {
        float v = xr[i];
        orow[i] = (v - mu) * rs * gam[i] + bet[i];
    }
}

// ---------------------------------------------------------------------------
// Strided-batched SIMT GEMM: C = alpha * A @ B (or A @ B^T)
// 128x128 block tile, BK=8, 256 threads, 8x8 per thread.
// Requires M%128==0, N%128==0, K%8==0 (true for all shapes here).
// Batch z -> b = z/nheads, h = z%nheads; ptr += b*bX + h*hX.
// ---------------------------------------------------------------------------
template <bool TRANSB>
__global__ void __launch_bounds__(256) gemm_kernel(
    const float* __restrict__ A, const float* __restrict__ B,
    float* __restrict__ C,
    int M, int N, int K, int lda, int ldb, int ldc,
    long long hA, long long bA, long long hB, long long bB,
    long long hC, long long bC, int nheads, float alpha)
{
    const int z = blockIdx.z;
    const int bb = z / nheads, hh = z % nheads;
    A += (size_t)(bb * bA + hh * hA);
    B += (size_t)(bb * bB + hh * hB);
    C += (size_t)(bb * bC + hh * hC);

    const int bm = blockIdx.y << 7;
    const int bn = blockIdx.x << 7;

    __shared__ float As[8][132];
    __shared__ float Bs[8][132];

    const int tid  = threadIdx.x;
    const int arow = tid >> 1;
    const int acol = (tid & 1) << 2;
    const int tx = tid & 15, ty = tid >> 4;

    float acc[8][8];
    #pragma unroll
    for (int i = 0; i < 8; i++)
        #pragma unroll
        for (int j = 0; j < 8; j++) acc[i][j] = 0.f;

    const float* Aldg = A + (size_t)(bm + arow) * lda + acol;
    const float* Bldg_t = B + (size_t)(bn + arow) * ldb + acol;     // TRANSB path
    const int brow = tid >> 5, bcol = (tid & 31) << 2;
    const float* Bldg_n = B + (size_t)brow * ldb + bn + bcol;        // NN path

    for (int k0 = 0; k0 < K; k0 += 8) {
        float4 av = *(const float4*)(Aldg + k0);
        As[acol + 0][arow] = av.x;
        As[acol + 1][arow] = av.y;
        As[acol + 2][arow] = av.z;
        As[acol + 3][arow] = av.w;

        if (TRANSB) {
            float4 bv = *(const float4*)(Bldg_t + k0);
            Bs[acol + 0][arow] = bv.x;
            Bs[acol + 1][arow] = bv.y;
            Bs[acol + 2][arow] = bv.z;
            Bs[acol + 3][arow] = bv.w;
        } else {
            *(float4*)&Bs[brow][bcol] =
                *(const float4*)(Bldg_n + (size_t)k0 * ldb);
        }
        __syncthreads();

        #pragma unroll
        for (int kk = 0; kk < 8; kk++) {
            float a[8], bv[8];
            *(float4*)(a)      = *(const float4*)&As[kk][ty << 3];
            *(float4*)(a + 4)  = *(const float4*)&As[kk][(ty << 3) + 4];
            *(float4*)(bv)     = *(const float4*)&Bs[kk][tx << 3];
            *(float4*)(bv + 4) = *(const float4*)&Bs[kk][(tx << 3) + 4];
            #pragma unroll
            for (int i = 0; i < 8; i++)
                #pragma unroll
                for (int j = 0; j < 8; j++)
                    acc[i][j] += a[i] * bv[j];
        }
        __syncthreads();
    }

    #pragma unroll
    for (int i = 0; i < 8; i++) {
        size_t coff = (size_t)(bm + (ty << 3) + i) * ldc + bn + (tx << 3);
        float4 o0 = make_float4(acc[i][0] * alpha, acc[i][1] * alpha,
                                acc[i][2] * alpha, acc[i][3] * alpha);
        float4 o1 = make_float4(acc[i][4] * alpha, acc[i][5] * alpha,
                                acc[i][6] * alpha, acc[i][7] * alpha);
        *(float4*)(C + coff)     = o0;
        *(float4*)(C + coff + 4) = o1;
    }
}

// ---------------------------------------------------------------------------
// Row softmax over 2048 cols, values held in registers (one read, one write)
// ---------------------------------------------------------------------------
__global__ void __launch_bounds__(256) softmax_kernel(float* __restrict__ S)
{
    float* p = S + (size_t)blockIdx.x * 2048;
    const int tid = threadIdx.x;
    float v[8];
    float m = -1e30f;
    #pragma unroll
    for (int i = 0; i < 8; i++) {
        v[i] = p[i * 256 + tid];
        m = fmaxf(m, v[i]);
    }
    __shared__ float sm[8];
    #pragma unroll
    for (int o = 16; o > 0; o >>= 1)
        m = fmaxf(m, __shfl_xor_sync(0xffffffffu, m, o));
    int w = tid >> 5;
    if ((tid & 31) == 0) sm[w] = m;
    __syncthreads();
    if (tid < 8) {
        float t = sm[tid];
        #pragma unroll
        for (int o = 4; o > 0; o >>= 1)
            t = fmaxf(t, __shfl_xor_sync(0xffu, t, o));
        sm[tid] = t;
    }
    __syncthreads();
    m = sm[0];

    float sum = 0.f;
    #pragma unroll
    for (int i = 0; i < 8; i++) {
        v[i] = __expf(v[i] - m);
        sum += v[i];
    }
    __shared__ float ss[8];
    #pragma unroll
    for (int o = 16; o > 0; o >>= 1)
        sum += __shfl_xor_sync(0xffffffffu, sum, o);
    if ((tid & 31) == 0) ss[w] = sum;
    __syncthreads();
    if (tid < 8) {
        float t = ss[tid];
        #pragma unroll
        for (int o = 4; o > 0; o >>= 1)
            t += __shfl_xor_sync(0xffu, t, o);
        ss[tid] = t;
    }
    __syncthreads();
    float inv = 1.0f / ss[0];
    #pragma unroll
    for (int i = 0; i < 8; i++)
        p[i * 256 + tid] = v[i] * inv;
}

// ---------------------------------------------------------------------------
extern "C" void kernel_launch(void* const* d_in, const int* in_sizes, int n_in,
                              void* d_out, int out_size)
{
    const float* x      = (const float*)d_in[0];
    const float* lat    = (const float*)d_in[1];
    const float* w_q    = (const float*)d_in[2];
    const float* w_kv   = (const float*)d_in[3];
    const float* w_out  = (const float*)d_in[4];
    const float* ln1_g  = (const float*)d_in[5];
    const float* ln1_b  = (const float*)d_in[6];
    const float* ln2_g  = (const float*)d_in[7];
    const float* ln2_b  = (const float*)d_in[8];
    float* out = (float*)d_out;

    float *xn, *ln, *q, *kv, *S, *att;
    cudaGetSymbolAddress((void**)&xn,  g_xn);
    cudaGetSymbolAddress((void**)&ln,  g_ln);
    cudaGetSymbolAddress((void**)&q,   g_q);
    cudaGetSymbolAddress((void**)&kv,  g_kv);
    cudaGetSymbolAddress((void**)&S,   g_s);
    cudaGetSymbolAddress((void**)&att, g_at);

    const long long LLz = 0;

    // LayerNorms
    ln_kernel<<<B_SZ * N1, 256>>>(x,   ln1_g, ln1_b, xn, KV_DIM);
    ln_kernel<<<B_SZ * N2, 256>>>(lat, ln2_g, ln2_b, ln, DIM);

    // q = ln @ w_q : (4096 x 3072) @ (3072 x 2048)
    gemm_kernel<false><<<dim3(INNER / 128, (B_SZ * N2) / 128, 1), 256>>>(
        ln, w_q, q, B_SZ * N2, INNER, DIM, DIM, INNER, INNER,
        LLz, LLz, LLz, LLz, LLz, LLz, 1, 1.0f);

    // kv = xn @ w_kv : (4096 x 2048) @ (2048 x 4096)
    gemm_kernel<false><<<dim3((2 * INNER) / 128, (B_SZ * N1) / 128, 1), 256>>>(
        xn, w_kv, kv, B_SZ * N1, 2 * INNER, KV_DIM, KV_DIM, 2 * INNER, 2 * INNER,
        LLz, LLz, LLz, LLz, LLz, LLz, 1, 1.0f);

    // S[z] = alpha * q_h @ k_h^T : per (b,h): (2048 x 128) @ (128 x 2048)^T
    const float alpha = 0.08838834764831845f;  // 1/sqrt(128)
    gemm_kernel<true><<<dim3(N1 / 128, N2 / 128, B_SZ * HEADS), 256>>>(
        q, kv, S, N2, N1, DHEAD,
        INNER, 2 * INNER, N1,
        /*hA*/ DHEAD, /*bA*/ (long long)N2 * INNER,
        /*hB*/ DHEAD, /*bB*/ (long long)N1 * 2 * INNER,
        /*hC*/ (long long)N2 * N1, /*bC*/ (long long)HEADS * N2 * N1,
        HEADS, alpha);

    // softmax over rows of S
    softmax_kernel<<<B_SZ * HEADS * N2, 256>>>(S);

    // att_h = P @ v_h : (2048 x 2048) @ (2048 x 128)
    gemm_kernel<false><<<dim3(1, N2 / 128, B_SZ * HEADS), 256>>>(
        S, kv + INNER, att, N2, DHEAD, N1,
        N1, 2 * INNER, INNER,
        /*hA*/ (long long)N2 * N1, /*bA*/ (long long)HEADS * N2 * N1,
        /*hB*/ DHEAD, /*bB*/ (long long)N1 * 2 * INNER,
        /*hC*/ DHEAD, /*bC*/ (long long)N2 * INNER,
        HEADS, 1.0f);

    // out = att @ w_out : (4096 x 2048) @ (2048 x 3072)
    gemm_kernel<false><<<dim3(DIM / 128, (B_SZ * N2) / 128, 1), 256>>>(
        att, w_out, out, B_SZ * N2, DIM, INNER, INNER, DIM, DIM,
        LLz, LLz, LLz, LLz, LLz, LLz, 1, 1.0f);
}

// round 6
// speedup vs baseline: 2.7290x; 2.7290x over previous
#include <cuda_runtime.h>
#include <cuda_bf16.h>
#include <cstdint>

// ===========================================================================
// PerceiverAttentionCA — tensor-core path via mma.sync (tf32, sm_80+ ISA;
// tcgen05 unusable: harness PTX target is sm_103 without the 'a' suffix).
// R6: identical to R4/R5 (two infra failures — resubmitting for evidence).
// ===========================================================================

#define B_SZ 2
#define N1 2048
#define N2 2048
#define DIM 3072
#define KV_DIM 2048
#define HEADS 16
#define DHEAD 128
#define INNER 2048

// ---------------- scratch (static device globals) ----------------
__device__ __align__(16) float g_xn  [(size_t)B_SZ * N1 * KV_DIM];
__device__ __align__(16) float g_ln  [(size_t)B_SZ * N2 * DIM];
__device__ __align__(16) float g_q   [(size_t)B_SZ * N2 * INNER];
__device__ __align__(16) float g_kv  [(size_t)B_SZ * N1 * 2 * INNER];
__device__ __align__(16) float g_s   [(size_t)B_SZ * HEADS * N2 * N1];
__device__ __align__(16) float g_at  [(size_t)B_SZ * N2 * INNER];
__device__ __align__(16) float g_wqT [(size_t)INNER * DIM];
__device__ __align__(16) float g_wkvT[(size_t)2 * INNER * KV_DIM];
__device__ __align__(16) float g_woT [(size_t)DIM * INNER];
__device__ __align__(16) float g_vt  [(size_t)B_SZ * INNER * N1];

__device__ __forceinline__ uint32_t f2tf32(float f) {
    uint32_t o; asm("cvt.rna.tf32.f32 %0, %1;" : "=r"(o) : "f"(f)); return o;
}

__device__ __forceinline__ void mma_tf32(float* d, const uint32_t* a,
                                         const uint32_t* b) {
    asm volatile(
        "mma.sync.aligned.m16n8k8.row.col.f32.tf32.tf32.f32 "
        "{%0,%1,%2,%3}, {%4,%5,%6,%7}, {%8,%9}, {%0,%1,%2,%3};"
        : "+f"(d[0]), "+f"(d[1]), "+f"(d[2]), "+f"(d[3])
        : "r"(a[0]), "r"(a[1]), "r"(a[2]), "r"(a[3]), "r"(b[0]), "r"(b[1]));
}

// ---------------------------------------------------------------------------
// SMEM fragment layout:
//  A: 32 tiles (8 m16-tiles x 4 k8-steps), tile = 32 lanes x 4 regs,
//     stride 132 floats -> fragment load = one LDS.128.
//  B: 64 tiles (16 n8-tiles x 4 k8-steps), tile = 32 lanes x 2 regs,
//     stride 68 floats  -> fragment load = one LDS.64.
// ---------------------------------------------------------------------------
#define A_TS 132
#define B_TS 68
#define A_STAGE (32 * A_TS)
#define B_STAGE (64 * B_TS)
#define STAGE_FLOATS (A_STAGE + B_STAGE)
#define GEMM_SMEM_BYTES (2 * STAGE_FLOATS * 4)

// C = alpha * A @ B^T ; A:[M,K] K-major, B:[N,K] K-major.
// grid = (N/128, M/128, batch); batch z -> (z/nheads, z%nheads) strides.
__global__ void __launch_bounds__(256, 1) hmma_gemm(
    const float* __restrict__ A, const float* __restrict__ B,
    float* __restrict__ C,
    int K, int lda, int ldb, int ldc,
    long long hA, long long bA, long long hB, long long bB,
    long long hC, long long bC, int nheads, float alpha)
{
    extern __shared__ uint32_t smem[];
    const int tid = threadIdx.x;
    const int lid = tid & 31, wid = tid >> 5;
    const int wm = wid >> 2, wn = wid & 3;

    const int z = blockIdx.z;
    const int bbz = z / nheads, hhz = z % nheads;
    A += (size_t)bbz * bA + (size_t)hhz * hA;
    B += (size_t)bbz * bB + (size_t)hhz * hB;
    C += (size_t)bbz * bC + (size_t)hhz * hC;
    const int bm = blockIdx.y << 7, bn = blockIdx.x << 7;

    // ---- staging geometry ----
    const int r0 = tid >> 3;           // 0..31
    const int kq = tid & 7;            // 0..7 (k-quad: 4 consecutive k)
    const int ks_w = kq >> 1;          // k8-step of this quad
    const int rka = (kq & 1) << 1;     // A reg offset from (k&4)
    const int rkb = kq & 1;            // B reg offset from (k&4)

    int offA[4], offB[4];
    #pragma unroll
    for (int i = 0; i < 4; i++) {
        int row = r0 + (i << 5);
        offA[i] = (((row >> 4) << 2) + ks_w) * A_TS +
                  ((row & 7) << 4) + ((row >> 3) & 1) + rka;
        offB[i] = (((row >> 3) << 2) + ks_w) * B_TS +
                  ((row & 7) << 3) + rkb;
    }

    const float* Aldg = A + (size_t)(bm + r0) * lda + (kq << 2);
    const float* Bldg = B + (size_t)(bn + r0) * ldb + (kq << 2);

    float acc[4][4][4];
    #pragma unroll
    for (int i = 0; i < 4; i++)
        #pragma unroll
        for (int j = 0; j < 4; j++)
            #pragma unroll
            for (int r = 0; r < 4; r++) acc[i][j][r] = 0.f;

    const int S = K >> 5;
    float4 av[4], bv[4];

    // prologue: stage 0 (rows r0+32i, k-cols kq*4..kq*4+3)
    #pragma unroll
    for (int i = 0; i < 4; i++) {
        av[i] = *(const float4*)(Aldg + (size_t)(i << 5) * lda);
        bv[i] = *(const float4*)(Bldg + (size_t)(i << 5) * ldb);
    }
    {
        uint32_t* sA = smem;
        uint32_t* sB = smem + A_STAGE;
        #pragma unroll
        for (int i = 0; i < 4; i++) {
            sA[offA[i] + 0]  = f2tf32(av[i].x);
            sA[offA[i] + 4]  = f2tf32(av[i].y);
            sA[offA[i] + 8]  = f2tf32(av[i].z);
            sA[offA[i] + 12] = f2tf32(av[i].w);
            sB[offB[i] + 0]  = f2tf32(bv[i].x);
            sB[offB[i] + 2]  = f2tf32(bv[i].y);
            sB[offB[i] + 4]  = f2tf32(bv[i].z);
            sB[offB[i] + 6]  = f2tf32(bv[i].w);
        }
    }
    __syncthreads();

    for (int s = 0; s < S; s++) {
        const int b = s & 1;
        if (s + 1 < S) {
            const int k0 = (s + 1) << 5;   // K-offset: contiguous, NOT scaled by ld
            #pragma unroll
            for (int i = 0; i < 4; i++) {
                av[i] = *(const float4*)(Aldg + k0 + (size_t)(i << 5) * lda);
                bv[i] = *(const float4*)(Bldg + k0 + (size_t)(i << 5) * ldb);
            }
        }

        // compute on buffer b
        {
            const uint32_t* sA = smem + b * STAGE_FLOATS;
            const uint32_t* sB = sA + A_STAGE;
            #pragma unroll
            for (int ks = 0; ks < 4; ks++) {
                uint32_t Af[4][4], Bf[4][2];
                #pragma unroll
                for (int mt = 0; mt < 4; mt++)
                    *(uint4*)Af[mt] = *(const uint4*)
                        &sA[((((wm << 2) + mt) << 2) + ks) * A_TS + (lid << 2)];
                #pragma unroll
                for (int nt = 0; nt < 4; nt++)
                    *(uint2*)Bf[nt] = *(const uint2*)
                        &sB[((((wn << 2) + nt) << 2) + ks) * B_TS + (lid << 1)];
                #pragma unroll
                for (int mt = 0; mt < 4; mt++)
                    #pragma unroll
                    for (int nt = 0; nt < 4; nt++)
                        mma_tf32(acc[mt][nt], Af[mt], Bf[nt]);
            }
        }

        if (s + 1 < S) {
            __syncthreads();
            uint32_t* sA = smem + (b ^ 1) * STAGE_FLOATS;
            uint32_t* sB = sA + A_STAGE;
            #pragma unroll
            for (int i = 0; i < 4; i++) {
                sA[offA[i] + 0]  = f2tf32(av[i].x);
                sA[offA[i] + 4]  = f2tf32(av[i].y);
                sA[offA[i] + 8]  = f2tf32(av[i].z);
                sA[offA[i] + 12] = f2tf32(av[i].w);
                sB[offB[i] + 0]  = f2tf32(bv[i].x);
                sB[offB[i] + 2]  = f2tf32(bv[i].y);
                sB[offB[i] + 4]  = f2tf32(bv[i].z);
                sB[offB[i] + 6]  = f2tf32(bv[i].w);
            }
            __syncthreads();
        }
    }

    // epilogue
    const int mrow = bm + (wm << 6);
    const int ncol = bn + (wn << 5);
    #pragma unroll
    for (int mt = 0; mt < 4; mt++) {
        #pragma unroll
        for (int nt = 0; nt < 4; nt++) {
            int r = mrow + (mt << 4) + (lid >> 2);
            int c = ncol + (nt << 3) + ((lid & 3) << 1);
            float2 v0, v1;
            v0.x = acc[mt][nt][0] * alpha; v0.y = acc[mt][nt][1] * alpha;
            v1.x = acc[mt][nt][2] * alpha; v1.y = acc[mt][nt][3] * alpha;
            *(float2*)(C + (size_t)r * ldc + c)       = v0;
            *(float2*)(C + (size_t)(r + 8) * ldc + c) = v1;
        }
    }
}

// ---------------------------------------------------------------------------
// LayerNorm
// ---------------------------------------------------------------------------
__global__ void __launch_bounds__(256) ln_kernel(
    const float* __restrict__ x, const float* __restrict__ gam,
    const float* __restrict__ bet, float* __restrict__ out, int cols)
{
    const int row = blockIdx.x;
    const float* xr = x + (size_t)row * cols;
    float* orow = out + (size_t)row * cols;

    float s = 0.f, s2 = 0.f;
    for (int i = threadIdx.x; i < cols; i += blockDim.x) {
        float v = xr[i]; s += v; s2 += v * v;
    }
    __shared__ float sm0[8], sm1[8];
    #pragma unroll
    for (int o = 16; o > 0; o >>= 1) {
        s  += __shfl_down_sync(0xffffffffu, s,  o);
        s2 += __shfl_down_sync(0xffffffffu, s2, o);
    }
    int w = threadIdx.x >> 5, l = threadIdx.x & 31;
    if (l == 0) { sm0[w] = s; sm1[w] = s2; }
    __syncthreads();
    if (threadIdx.x == 0) {
        float ts = 0.f, t2 = 0.f;
        #pragma unroll
        for (int i = 0; i < 8; i++) { ts += sm0[i]; t2 += sm1[i]; }
        float mu  = ts / (float)cols;
        float var = t2 / (float)cols - mu * mu;
        sm0[0] = mu; sm1[0] = rsqrtf(var + 1e-5f);
    }
    __syncthreads();
    float mu = sm0[0], rs = sm1[0];
    for (int i = threadIdx.x; i < cols; i += blockDim.x) {
        float v = xr[i];
        orow[i] = (v - mu) * rs * gam[i] + bet[i];
    }
}

// ---------------------------------------------------------------------------
// Batched 32x32 tiled transpose
// ---------------------------------------------------------------------------
__global__ void transpose_kernel(
    const float* __restrict__ in, float* __restrict__ out,
    int ldi, int ldo,
    long long hI, long long bI, long long hO, long long bO, int nheads)
{
    __shared__ float t[32][33];
    const int z = blockIdx.z;
    const int bb = z / nheads, hh = z % nheads;
    in  += (size_t)bb * bI + (size_t)hh * hI;
    out += (size_t)bb * bO + (size_t)hh * hO;
    int x = blockIdx.x * 32 + threadIdx.x;
    int y = blockIdx.y * 32 + threadIdx.y;
    #pragma unroll
    for (int j = 0; j < 32; j += 8)
        t[threadIdx.y + j][threadIdx.x] = in[(size_t)(y + j) * ldi + x];
    __syncthreads();
    int x2 = blockIdx.y * 32 + threadIdx.x;
    int y2 = blockIdx.x * 32 + threadIdx.y;
    #pragma unroll
    for (int j = 0; j < 32; j += 8)
        out[(size_t)(y2 + j) * ldo + x2] = t[threadIdx.x][threadIdx.y + j];
}

// ---------------------------------------------------------------------------
// Row softmax over 2048 cols
// ---------------------------------------------------------------------------
__global__ void __launch_bounds__(256) softmax_kernel(float* __restrict__ S)
{
    float* p = S + (size_t)blockIdx.x * 2048;
    const int tid = threadIdx.x;
    float v[8];
    float m = -1e30f;
    #pragma unroll
    for (int i = 0; i < 8; i++) { v[i] = p[i * 256 + tid]; m = fmaxf(m, v[i]); }
    __shared__ float sm[8];
    #pragma unroll
    for (int o = 16; o > 0; o >>= 1)
        m = fmaxf(m, __shfl_xor_sync(0xffffffffu, m, o));
    int w = tid >> 5;
    if ((tid & 31) == 0) sm[w] = m;
    __syncthreads();
    if (tid < 8) {
        float t = sm[tid];
        #pragma unroll
        for (int o = 4; o > 0; o >>= 1)
            t = fmaxf(t, __shfl_xor_sync(0xffu, t, o));
        sm[tid] = t;
    }
    __syncthreads();
    m = sm[0];
    float sum = 0.f;
    #pragma unroll
    for (int i = 0; i < 8; i++) { v[i] = __expf(v[i] - m); sum += v[i]; }
    __shared__ float ss[8];
    #pragma unroll
    for (int o = 16; o > 0; o >>= 1)
        sum += __shfl_xor_sync(0xffffffffu, sum, o);
    if ((tid & 31) == 0) ss[w] = sum;
    __syncthreads();
    if (tid < 8) {
        float t = ss[tid];
        #pragma unroll
        for (int o = 4; o > 0; o >>= 1)
            t += __shfl_xor_sync(0xffu, t, o);
        ss[tid] = t;
    }
    __syncthreads();
    float inv = 1.0f / ss[0];
    #pragma unroll
    for (int i = 0; i < 8; i++) p[i * 256 + tid] = v[i] * inv;
}

// ---------------------------------------------------------------------------
extern "C" void kernel_launch(void* const* d_in, const int* in_sizes, int n_in,
                              void* d_out, int out_size)
{
    const float* x      = (const float*)d_in[0];
    const float* lat    = (const float*)d_in[1];
    const float* w_q    = (const float*)d_in[2];
    const float* w_kv   = (const float*)d_in[3];
    const float* w_out  = (const float*)d_in[4];
    const float* ln1_g  = (const float*)d_in[5];
    const float* ln1_b  = (const float*)d_in[6];
    const float* ln2_g  = (const float*)d_in[7];
    const float* ln2_b  = (const float*)d_in[8];
    float* out = (float*)d_out;

    float *xn, *ln, *q, *kv, *S, *att, *wqT, *wkvT, *woT, *vt;
    cudaGetSymbolAddress((void**)&xn,   g_xn);
    cudaGetSymbolAddress((void**)&ln,   g_ln);
    cudaGetSymbolAddress((void**)&q,    g_q);
    cudaGetSymbolAddress((void**)&kv,   g_kv);
    cudaGetSymbolAddress((void**)&S,    g_s);
    cudaGetSymbolAddress((void**)&att,  g_at);
    cudaGetSymbolAddress((void**)&wqT,  g_wqT);
    cudaGetSymbolAddress((void**)&wkvT, g_wkvT);
    cudaGetSymbolAddress((void**)&woT,  g_woT);
    cudaGetSymbolAddress((void**)&vt,   g_vt);

    cudaFuncSetAttribute(hmma_gemm, cudaFuncAttributeMaxDynamicSharedMemorySize,
                         GEMM_SMEM_BYTES);

    const dim3 tb(32, 8);

    // LayerNorms
    ln_kernel<<<B_SZ * N1, 256>>>(x,   ln1_g, ln1_b, xn, KV_DIM);
    ln_kernel<<<B_SZ * N2, 256>>>(lat, ln2_g, ln2_b, ln, DIM);

    // weight transposes (K-major B operands)
    transpose_kernel<<<dim3(INNER / 32, DIM / 32, 1), tb>>>(
        w_q, wqT, INNER, DIM, 0, 0, 0, 0, 1);
    transpose_kernel<<<dim3((2 * INNER) / 32, KV_DIM / 32, 1), tb>>>(
        w_kv, wkvT, 2 * INNER, KV_DIM, 0, 0, 0, 0, 1);
    transpose_kernel<<<dim3(DIM / 32, INNER / 32, 1), tb>>>(
        w_out, woT, DIM, INNER, 0, 0, 0, 0, 1);

    // q = ln @ w_q  : M=4096 N=2048 K=3072
    hmma_gemm<<<dim3(INNER / 128, (B_SZ * N2) / 128, 1), 256, GEMM_SMEM_BYTES>>>(
        ln, wqT, q, DIM, DIM, DIM, INNER,
        0, 0, 0, 0, 0, 0, 1, 1.0f);

    // kv = xn @ w_kv : M=4096 N=4096 K=2048
    hmma_gemm<<<dim3((2 * INNER) / 128, (B_SZ * N1) / 128, 1), 256, GEMM_SMEM_BYTES>>>(
        xn, wkvT, kv, KV_DIM, KV_DIM, KV_DIM, 2 * INNER,
        0, 0, 0, 0, 0, 0, 1, 1.0f);

    // v^T per (b,h): vt[b][h][d][n1]
    transpose_kernel<<<dim3(DHEAD / 32, N1 / 32, B_SZ * HEADS), tb>>>(
        kv + INNER, vt, 2 * INNER, N1,
        /*hI*/ DHEAD, /*bI*/ (long long)N1 * 2 * INNER,
        /*hO*/ (long long)DHEAD * N1, /*bO*/ (long long)INNER * N1, HEADS);

    // S = alpha * q @ k^T per (b,h): M=2048 N=2048 K=128
    hmma_gemm<<<dim3(N1 / 128, N2 / 128, B_SZ * HEADS), 256, GEMM_SMEM_BYTES>>>(
        q, kv, S, DHEAD, INNER, 2 * INNER, N1,
        /*hA*/ DHEAD, /*bA*/ (long long)N2 * INNER,
        /*hB*/ DHEAD, /*bB*/ (long long)N1 * 2 * INNER,
        /*hC*/ (long long)N2 * N1, /*bC*/ (long long)HEADS * N2 * N1,
        HEADS, 0.08838834764831845f);

    // softmax
    softmax_kernel<<<B_SZ * HEADS * N2, 256>>>(S);

    // att = P @ v per (b,h): M=2048 N=128 K=2048  (B = vt, K-major)
    hmma_gemm<<<dim3(1, N2 / 128, B_SZ * HEADS), 256, GEMM_SMEM_BYTES>>>(
        S, vt, att, N1, N1, N1, INNER,
        /*hA*/ (long long)N2 * N1, /*bA*/ (long long)HEADS * N2 * N1,
        /*hB*/ (long long)DHEAD * N1, /*bB*/ (long long)INNER * N1,
        /*hC*/ DHEAD, /*bC*/ (long long)N2 * INNER,
        HEADS, 1.0f);

    // out = att @ w_out : M=4096 N=3072 K=2048
    hmma_gemm<<<dim3(DIM / 128, (B_SZ * N2) / 128, 1), 256, GEMM_SMEM_BYTES>>>(
        att, woT, out, INNER, INNER, INNER, DIM,
        0, 0, 0, 0, 0, 0, 1, 1.0f);
}